// round 3
// baseline (speedup 1.0000x reference)
#include <cuda_runtime.h>

#define NMAX 100000
#define D 32

// ---- persistent scratch (device globals; no allocation in kernel_launch) ----
__device__ float  d_g[(size_t)NMAX * D];    // g = h2 * dinv  (gather source)
__device__ float  d_acc[(size_t)NMAX * D];  // accumulator, init = g (self loop)
__device__ float  d_dinv[NMAX];
__device__ int    d_deg[NMAX];
__device__ double d_stats[5];               // Sx0, Sx1, Sx0^2, Sx1^2, Sx0x1
__device__ float  d_A[2 * D];               // folded (scale * w1)
__device__ float  d_B[D];                   // folded bias
__device__ float  d_v[D];                   // gcn_w^T @ wb
__device__ float  d_C;                      // wb . gcn_b + bb

// ---------------------------------------------------------------------------
__global__ void zero_k(int n) {
    int i = blockIdx.x * blockDim.x + threadIdx.x;
    if (i < n) d_deg[i] = 0;
    if (i < 5) d_stats[i] = 0.0;
}

// in-degree histogram over dst (edge_index is int32: JAX x64 is disabled)
__global__ void deg_k(const int* __restrict__ dst, int E) {
    int i = blockIdx.x * blockDim.x + threadIdx.x;
    if (i < E) atomicAdd(&d_deg[dst[i]], 1);
}

// moments of x: per-thread accumulate, warp reduce, one double atomic per warp
__global__ void stats_k(const float* __restrict__ x, int n) {
    int i = blockIdx.x * blockDim.x + threadIdx.x;
    float a = 0.f, b = 0.f;
    if (i < n) { a = x[2 * i]; b = x[2 * i + 1]; }
    float s0 = a, s1 = b, s00 = a * a, s11 = b * b, s01 = a * b;
#pragma unroll
    for (int o = 16; o; o >>= 1) {
        s0  += __shfl_xor_sync(0xffffffffu, s0,  o);
        s1  += __shfl_xor_sync(0xffffffffu, s1,  o);
        s00 += __shfl_xor_sync(0xffffffffu, s00, o);
        s11 += __shfl_xor_sync(0xffffffffu, s11, o);
        s01 += __shfl_xor_sync(0xffffffffu, s01, o);
    }
    if ((threadIdx.x & 31) == 0) {
        atomicAdd(&d_stats[0], (double)s0);
        atomicAdd(&d_stats[1], (double)s1);
        atomicAdd(&d_stats[2], (double)s00);
        atomicAdd(&d_stats[3], (double)s11);
        atomicAdd(&d_stats[4], (double)s01);
    }
}

// fold BN into (A, B); fold head into (v, C)
__global__ void prep_k(const float* __restrict__ w1, const float* __restrict__ b1,
                       const float* __restrict__ gam, const float* __restrict__ bet,
                       const float* __restrict__ gw, const float* __restrict__ gb,
                       const float* __restrict__ wb, const float* __restrict__ bb,
                       int n) {
    int c = threadIdx.x;
    if (c >= D) return;
    double invN = 1.0 / (double)n;
    double m0 = d_stats[0] * invN, m1 = d_stats[1] * invN;
    double v00 = d_stats[2] * invN - m0 * m0;
    double v11 = d_stats[3] * invN - m1 * m1;
    double v01 = d_stats[4] * invN - m0 * m1;
    float a0 = w1[2 * c], a1 = w1[2 * c + 1];
    float mean = (float)((double)a0 * m0 + (double)a1 * m1) + b1[c];
    float var  = (float)((double)a0 * a0 * v00 + 2.0 * (double)a0 * a1 * v01 +
                         (double)a1 * a1 * v11);
    float scale = gam[c] * rsqrtf(var + 1e-5f);
    d_A[2 * c]     = a0 * scale;
    d_A[2 * c + 1] = a1 * scale;
    d_B[c] = b1[c] * scale + bet[c] - mean * scale;
    float vk = 0.f;
#pragma unroll
    for (int r = 0; r < D; r++) vk += wb[r] * gw[r * D + c];
    d_v[c] = vk;
    if (c == 0) {
        float C = bb[0];
#pragma unroll
        for (int r = 0; r < D; r++) C += wb[r] * gb[r];
        d_C = C;
    }
}

// encoder: x -> folded-BN -> PReLU -> W2 -> *dinv ; smem-staged coalesced stores
__global__ void __launch_bounds__(256) encode_k(
    const float* __restrict__ x, const float* __restrict__ w2,
    const float* __restrict__ b2, const float* __restrict__ pa, int n) {
    __shared__ float sw2[D * D];      // 4KB
    __shared__ float sA[2 * D], sB[D], sb2[D];
    __shared__ float stg[256 * 33];   // padded staging (33.8KB)
    int t = threadIdx.x;
    for (int i = t; i < D * D; i += 256) sw2[i] = w2[i];
    if (t < D)     { sB[t] = d_B[t]; sb2[t] = b2[t]; }
    if (t < 2 * D) sA[t] = d_A[t];
    float alpha = pa[0];
    __syncthreads();

    int node = blockIdx.x * 256 + t;
    if (node < n) {
        float x0 = x[2 * node], x1 = x[2 * node + 1];
        float p[D];
#pragma unroll
        for (int k = 0; k < D; k++) {
            float h = fmaf(sA[2 * k], x0, fmaf(sA[2 * k + 1], x1, sB[k]));
            p[k] = h >= 0.f ? h : alpha * h;
        }
        float dv = rsqrtf((float)d_deg[node] + 1.0f);
        d_dinv[node] = dv;
        const float4* w2v = (const float4*)sw2;  // [32][8] float4
#pragma unroll
        for (int c = 0; c < D; c++) {
            float acc = sb2[c];
#pragma unroll
            for (int k8 = 0; k8 < 8; k8++) {
                float4 w = w2v[c * 8 + k8];
                acc = fmaf(w.x, p[4 * k8], acc);
                acc = fmaf(w.y, p[4 * k8 + 1], acc);
                acc = fmaf(w.z, p[4 * k8 + 2], acc);
                acc = fmaf(w.w, p[4 * k8 + 3], acc);
            }
            stg[t * 33 + c] = acc * dv;
        }
    }
    __syncthreads();
    // coalesced stores: g and acc (acc starts as g => self-loop term prefolded)
    size_t base = (size_t)blockIdx.x * 256 * D;
    float4* gp = (float4*)(d_g + base);
    float4* ap = (float4*)(d_acc + base);
#pragma unroll
    for (int j = 0; j < 8; j++) {
        int f = j * 256 + t;
        int o = f * 4;
        int nl = o >> 5, c = o & 31;
        if (blockIdx.x * 256 + nl < n) {
            float4 v4 = make_float4(stg[nl * 33 + c], stg[nl * 33 + c + 1],
                                    stg[nl * 33 + c + 2], stg[nl * 33 + c + 3]);
            gp[f] = v4;
            ap[f] = v4;
        }
    }
}

// edge scatter: 8 threads/edge, one float4 gather + one v4 red each
__global__ void __launch_bounds__(256) scatter_k(const int* __restrict__ ei, int E) {
    unsigned int tid = blockIdx.x * 256u + threadIdx.x;
    unsigned int total = (unsigned int)E * 8u;
    if (tid >= total) return;
    unsigned int e = tid >> 3;
    unsigned int c = (tid & 7u) << 2;
    int s = ei[e];
    int d = ei[(size_t)E + e];
    const float4 m = *(const float4*)(d_g + (size_t)s * D + c);
    float* dp = d_acc + (size_t)d * D + c;
    asm volatile("red.global.add.v4.f32 [%0], {%1,%2,%3,%4};"
                 :: "l"(dp), "f"(m.x), "f"(m.y), "f"(m.z), "f"(m.w)
                 : "memory");
}

// score head: out[n] = C + dinv[n] * (v . acc[n])
__global__ void __launch_bounds__(256) score_k(float* __restrict__ out, int n) {
    int tid = blockIdx.x * 256 + threadIdx.x;
    int node = tid >> 3;
    int c = (tid & 7) << 2;
    if (node >= n) return;
    float4 a = *(const float4*)(d_acc + (size_t)node * D + c);
    float4 vv = *(const float4*)(d_v + c);
    float part = vv.x * a.x + vv.y * a.y + vv.z * a.z + vv.w * a.w;
    part += __shfl_xor_sync(0xffffffffu, part, 4);
    part += __shfl_xor_sync(0xffffffffu, part, 2);
    part += __shfl_xor_sync(0xffffffffu, part, 1);
    if ((tid & 7) == 0) out[node] = d_C + d_dinv[node] * part;
}

// ---------------------------------------------------------------------------
extern "C" void kernel_launch(void* const* d_in, const int* in_sizes, int n_in,
                              void* d_out, int out_size) {
    const float* x   = (const float*)d_in[0];
    const int*   ei  = (const int*)d_in[1];      // int32: JAX x64 disabled
    const float* w1  = (const float*)d_in[2];
    const float* b1  = (const float*)d_in[3];
    const float* gam = (const float*)d_in[4];
    const float* bet = (const float*)d_in[5];
    const float* pa  = (const float*)d_in[6];
    const float* w2  = (const float*)d_in[7];
    const float* b2  = (const float*)d_in[8];
    const float* gw  = (const float*)d_in[9];
    const float* gb  = (const float*)d_in[10];
    const float* wb  = (const float*)d_in[11];
    const float* bb  = (const float*)d_in[12];
    int n = in_sizes[0] / 2;
    int E = in_sizes[1] / 2;

    int nb = (n + 255) / 256;
    zero_k<<<nb, 256>>>(n);
    deg_k<<<(E + 255) / 256, 256>>>(ei + E, E);
    stats_k<<<nb, 256>>>(x, n);
    prep_k<<<1, 32>>>(w1, b1, gam, bet, gw, gb, wb, bb, n);
    encode_k<<<nb, 256>>>(x, w2, b2, pa, n);
    unsigned int sthreads = (unsigned int)E * 8u;
    scatter_k<<<(sthreads + 255u) / 256u, 256>>>(ei, E);
    score_k<<<(n * 8 + 255) / 256, 256>>>((float*)d_out, n);
}

// round 4
// speedup vs baseline: 1.7483x; 1.7483x over previous
#include <cuda_runtime.h>

#define NMAX 100000
#define D 32
#define NB ((NMAX + 255) / 256)   // 391 blocks for node-range kernels

// ---- persistent scratch (device globals; no allocation anywhere) ----
__device__ float  d_q[NMAX];       // q[n] = dinv[n] * (u . p[n] + c2)
__device__ float  d_sacc[NMAX];    // scalar accumulator, init = q (self loop)
__device__ float  d_dinv[NMAX];
__device__ int    d_deg[NMAX];
__device__ double d_part[NB][5];   // per-block x-moment partials
__device__ float  d_C;             // wb . gcn_b + bb

// ---------------------------------------------------------------------------
// stats_k: zero deg[] (plain stores) + per-block x moments (no global atomics)
__global__ void __launch_bounds__(256) stats_k(const float* __restrict__ x, int n) {
    __shared__ double sred[8][5];
    int t = threadIdx.x;
    int i = blockIdx.x * 256 + t;
    float a = 0.f, b = 0.f;
    if (i < n) { a = x[2 * i]; b = x[2 * i + 1]; d_deg[i] = 0; }
    float s[5] = { a, b, a * a, b * b, a * b };
#pragma unroll
    for (int o = 16; o; o >>= 1)
#pragma unroll
        for (int j = 0; j < 5; j++) s[j] += __shfl_xor_sync(0xffffffffu, s[j], o);
    if ((t & 31) == 0)
#pragma unroll
        for (int j = 0; j < 5; j++) sred[t >> 5][j] = (double)s[j];
    __syncthreads();
    if (t < 5) {
        double acc = 0.0;
#pragma unroll
        for (int w = 0; w < 8; w++) acc += sred[w][t];
        d_part[blockIdx.x][t] = acc;
    }
}

// deg_k: in-degree histogram over dst, 4 edges per thread
__global__ void __launch_bounds__(256) deg_k(const int* __restrict__ dst, int E4, int Etail) {
    int i = blockIdx.x * 256 + threadIdx.x;
    if (i < E4) {
        int4 dd = ((const int4*)dst)[i];
        atomicAdd(&d_deg[dd.x], 1);
        atomicAdd(&d_deg[dd.y], 1);
        atomicAdd(&d_deg[dd.z], 1);
        atomicAdd(&d_deg[dd.w], 1);
    }
    if (i == 0)
        for (int k = 0; k < Etail; k++) atomicAdd(&d_deg[dst[E4 * 4 + k]], 1);
}

// encode_k: fold everything (BN, v, u, c2, C) in warp0, then per-node q
__global__ void __launch_bounds__(256) encode_k(
    const float* __restrict__ x,
    const float* __restrict__ w1, const float* __restrict__ b1,
    const float* __restrict__ gam, const float* __restrict__ bet,
    const float* __restrict__ pa,
    const float* __restrict__ w2, const float* __restrict__ b2,
    const float* __restrict__ gw, const float* __restrict__ gb,
    const float* __restrict__ wb, const float* __restrict__ bb,
    int n) {
    __shared__ float sA[2 * D], sB[D], sU[D], sV[D];
    __shared__ float sc2;
    __shared__ double sst[5];
    int t = threadIdx.x;
    int nblk = gridDim.x;

    if (t < 5) {  // reduce stats partials (L2-cached)
        double acc = 0.0;
        for (int b = 0; b < nblk; b++) acc += d_part[b][t];
        sst[t] = acc;
    }
    __syncthreads();

    if (t < D) {
        // BN fold
        double invN = 1.0 / (double)n;
        double m0 = sst[0] * invN, m1 = sst[1] * invN;
        double v00 = sst[2] * invN - m0 * m0;
        double v11 = sst[3] * invN - m1 * m1;
        double v01 = sst[4] * invN - m0 * m1;
        float a0 = w1[2 * t], a1 = w1[2 * t + 1];
        float mean = (float)((double)a0 * m0 + (double)a1 * m1) + b1[t];
        float var  = (float)((double)a0 * a0 * v00 + 2.0 * (double)a0 * a1 * v01 +
                             (double)a1 * a1 * v11);
        float scale = gam[t] * rsqrtf(var + 1e-5f);
        sA[2 * t]     = a0 * scale;
        sA[2 * t + 1] = a1 * scale;
        sB[t] = b1[t] * scale + bet[t] - mean * scale;
        // v = gcn_w^T @ wb
        float v = 0.f;
#pragma unroll
        for (int r = 0; r < D; r++) v = fmaf(wb[r], gw[r * D + t], v);
        sV[t] = v;
    }
    __syncthreads();
    if (t < D) {
        // u = w2^T @ v
        float u = 0.f;
#pragma unroll
        for (int r = 0; r < D; r++) u = fmaf(sV[r], w2[r * D + t], u);
        sU[t] = u;
        // c2 = v . b2 ; C = wb . gcn_b + bb
        float cc = sV[t] * b2[t];
        float Cc = wb[t] * gb[t];
#pragma unroll
        for (int o = 16; o; o >>= 1) {
            cc += __shfl_xor_sync(0xffffffffu, cc, o);
            Cc += __shfl_xor_sync(0xffffffffu, Cc, o);
        }
        if (t == 0) {
            sc2 = cc;
            if (blockIdx.x == 0) d_C = Cc + bb[0];
        }
    }
    __syncthreads();

    int node = blockIdx.x * 256 + t;
    if (node < n) {
        float x0 = x[2 * node], x1 = x[2 * node + 1];
        float alpha = pa[0];
        float dv = rsqrtf((float)d_deg[node] + 1.0f);
        float acc = sc2;
#pragma unroll
        for (int k = 0; k < D; k++) {
            float h = fmaf(sA[2 * k], x0, fmaf(sA[2 * k + 1], x1, sB[k]));
            float p = h >= 0.f ? h : alpha * h;
            acc = fmaf(sU[k], p, acc);
        }
        float qv = dv * acc;
        d_q[node] = qv;
        d_sacc[node] = qv;    // self-loop term prefolded
        d_dinv[node] = dv;
    }
}

// scatter_k: 4 edges per thread, scalar gather + scalar red
__global__ void __launch_bounds__(256) scatter_k(const int* __restrict__ ei, int E,
                                                 int E4, int Etail) {
    int i = blockIdx.x * 256 + threadIdx.x;
    if (i < E4) {
        int4 ss = ((const int4*)ei)[i];
        int4 dd = ((const int4*)(ei + E))[i];
        float q0 = __ldg(&d_q[ss.x]);
        float q1 = __ldg(&d_q[ss.y]);
        float q2 = __ldg(&d_q[ss.z]);
        float q3 = __ldg(&d_q[ss.w]);
        atomicAdd(&d_sacc[dd.x], q0);
        atomicAdd(&d_sacc[dd.y], q1);
        atomicAdd(&d_sacc[dd.z], q2);
        atomicAdd(&d_sacc[dd.w], q3);
    }
    if (i == 0)
        for (int k = 0; k < Etail; k++) {
            int e = E4 * 4 + k;
            atomicAdd(&d_sacc[ei[E + e]], __ldg(&d_q[ei[e]]));
        }
}

// score_k: out[n] = C + dinv[n] * sacc[n]
__global__ void __launch_bounds__(256) score_k(float* __restrict__ out, int n) {
    int i = blockIdx.x * 256 + threadIdx.x;
    if (i < n) out[i] = d_C + d_dinv[i] * d_sacc[i];
}

// ---------------------------------------------------------------------------
extern "C" void kernel_launch(void* const* d_in, const int* in_sizes, int n_in,
                              void* d_out, int out_size) {
    const float* x   = (const float*)d_in[0];
    const int*   ei  = (const int*)d_in[1];      // int32 (JAX x64 disabled)
    const float* w1  = (const float*)d_in[2];
    const float* b1  = (const float*)d_in[3];
    const float* gam = (const float*)d_in[4];
    const float* bet = (const float*)d_in[5];
    const float* pa  = (const float*)d_in[6];
    const float* w2  = (const float*)d_in[7];
    const float* b2  = (const float*)d_in[8];
    const float* gw  = (const float*)d_in[9];
    const float* gb  = (const float*)d_in[10];
    const float* wb  = (const float*)d_in[11];
    const float* bb  = (const float*)d_in[12];
    int n = in_sizes[0] / 2;
    int E = in_sizes[1] / 2;
    int E4 = E >> 2;          // int4-vectorized count (E=3.2M => exact)
    int Etail = E & 3;

    int nb = (n + 255) / 256;
    int eb4 = (E4 + 255) / 256;
    if (eb4 == 0) eb4 = 1;

    stats_k<<<nb, 256>>>(x, n);                       // also zeroes deg
    deg_k<<<eb4, 256>>>(ei + E, E4, Etail);
    encode_k<<<nb, 256>>>(x, w1, b1, gam, bet, pa, w2, b2, gw, gb, wb, bb, n);
    scatter_k<<<eb4, 256>>>(ei, E, E4, Etail);
    score_k<<<nb, 256>>>((float*)d_out, n);
}

// round 5
// speedup vs baseline: 2.3375x; 1.3370x over previous
#include <cuda_runtime.h>

#define NMAX 100000
#define D 32
#define NBN ((NMAX + 255) / 256)   // 391 node-blocks

// ---- persistent scratch (device globals; zero-initialized at load) ----
__device__ float  d_q[NMAX];        // q[n] = dinv[n] * (u . p[n] + c2)
__device__ float  d_sacc[NMAX];     // scalar accumulator, init = q (self loop)
__device__ float  d_dinv[NMAX];
__device__ int    d_deg[NMAX];      // starts 0; encode_k re-zeroes after read
__device__ double d_part[NBN][5];   // per-block x-moment partials
__device__ float  d_C;              // wb . gcn_b + bb

// ---------------------------------------------------------------------------
// degstats_k: in-degree histogram (8 edges/thread) + x-moment partials
// (first NBN blocks also handle one node slice each for stats)
__global__ void __launch_bounds__(256) degstats_k(
    const int* __restrict__ dst, int nT8, int Etail, int E,
    const float* __restrict__ x, int n, int nbn) {
    int t = threadIdx.x;
    int i = blockIdx.x * 256 + t;
    if (i < nT8) {
        const int4* d4 = (const int4*)dst;
        int4 a = __ldcs(&d4[2 * i]);
        int4 b = __ldcs(&d4[2 * i + 1]);
        atomicAdd(&d_deg[a.x], 1); atomicAdd(&d_deg[a.y], 1);
        atomicAdd(&d_deg[a.z], 1); atomicAdd(&d_deg[a.w], 1);
        atomicAdd(&d_deg[b.x], 1); atomicAdd(&d_deg[b.y], 1);
        atomicAdd(&d_deg[b.z], 1); atomicAdd(&d_deg[b.w], 1);
    }
    if (i == 0)
        for (int k = 0; k < Etail; k++) atomicAdd(&d_deg[dst[nT8 * 8 + k]], 1);

    // stats: first nbn blocks, one node per thread
    if (blockIdx.x < nbn) {
        __shared__ double sred[8][5];
        int node = blockIdx.x * 256 + t;
        float a = 0.f, b = 0.f;
        if (node < n) {
            float2 xv = ((const float2*)x)[node];
            a = xv.x; b = xv.y;
        }
        float s[5] = { a, b, a * a, b * b, a * b };
#pragma unroll
        for (int o = 16; o; o >>= 1)
#pragma unroll
            for (int j = 0; j < 5; j++) s[j] += __shfl_xor_sync(0xffffffffu, s[j], o);
        if ((t & 31) == 0)
#pragma unroll
            for (int j = 0; j < 5; j++) sred[t >> 5][j] = (double)s[j];
        __syncthreads();
        if (t < 5) {
            double acc = 0.0;
#pragma unroll
            for (int w = 0; w < 8; w++) acc += sred[w][t];
            d_part[blockIdx.x][t] = acc;
        }
    }
}

// encode_k: fold BN/v/u/c2/C, compute q per node, re-zero deg for next replay
__global__ void __launch_bounds__(256) encode_k(
    const float* __restrict__ x,
    const float* __restrict__ w1, const float* __restrict__ b1,
    const float* __restrict__ gam, const float* __restrict__ bet,
    const float* __restrict__ pa,
    const float* __restrict__ w2, const float* __restrict__ b2,
    const float* __restrict__ gw, const float* __restrict__ gb,
    const float* __restrict__ wb, const float* __restrict__ bb,
    int n, int nbn) {
    __shared__ float sA[2 * D], sB[D], sU[D], sV[D];
    __shared__ float sc2;
    __shared__ double sst[5];
    int t = threadIdx.x;

    // parallel reduce of stats partials: warp c (0..4) owns component c
    if (t < 160) {
        int c = t >> 5, k = t & 31;
        double a = 0.0;
        for (int b = k; b < nbn; b += 32) a += d_part[b][c];
#pragma unroll
        for (int o = 16; o; o >>= 1) a += __shfl_xor_sync(0xffffffffu, a, o);
        if (k == 0) sst[c] = a;
    }
    __syncthreads();

    if (t < D) {
        double invN = 1.0 / (double)n;
        double m0 = sst[0] * invN, m1 = sst[1] * invN;
        double v00 = sst[2] * invN - m0 * m0;
        double v11 = sst[3] * invN - m1 * m1;
        double v01 = sst[4] * invN - m0 * m1;
        float a0 = w1[2 * t], a1 = w1[2 * t + 1];
        float mean = (float)((double)a0 * m0 + (double)a1 * m1) + b1[t];
        float var  = (float)((double)a0 * a0 * v00 + 2.0 * (double)a0 * a1 * v01 +
                             (double)a1 * a1 * v11);
        float scale = gam[t] * rsqrtf(var + 1e-5f);
        sA[2 * t]     = a0 * scale;
        sA[2 * t + 1] = a1 * scale;
        sB[t] = b1[t] * scale + bet[t] - mean * scale;
        float v = 0.f;
#pragma unroll
        for (int r = 0; r < D; r++) v = fmaf(wb[r], gw[r * D + t], v);
        sV[t] = v;
    }
    __syncthreads();
    if (t < D) {
        float u = 0.f;
#pragma unroll
        for (int r = 0; r < D; r++) u = fmaf(sV[r], w2[r * D + t], u);
        sU[t] = u;
        float cc = sV[t] * b2[t];
        float Cc = wb[t] * gb[t];
#pragma unroll
        for (int o = 16; o; o >>= 1) {
            cc += __shfl_xor_sync(0xffffffffu, cc, o);
            Cc += __shfl_xor_sync(0xffffffffu, Cc, o);
        }
        if (t == 0) {
            sc2 = cc;
            if (blockIdx.x == 0) d_C = Cc + bb[0];
        }
    }
    __syncthreads();

    int node = blockIdx.x * 256 + t;
    if (node < n) {
        float2 xv = ((const float2*)x)[node];
        float alpha = pa[0];
        int dg = d_deg[node];
        d_deg[node] = 0;                      // re-zero for next graph replay
        float dv = rsqrtf((float)dg + 1.0f);
        float acc = sc2;
#pragma unroll
        for (int k = 0; k < D; k++) {
            float h = fmaf(sA[2 * k], xv.x, fmaf(sA[2 * k + 1], xv.y, sB[k]));
            float p = h >= 0.f ? h : alpha * h;
            acc = fmaf(sU[k], p, acc);
        }
        float qv = dv * acc;
        d_q[node] = qv;
        d_sacc[node] = qv;                    // self-loop prefolded
        d_dinv[node] = dv;
    }
}

// scatter_k: 8 edges/thread, scalar gather + scalar red
__global__ void __launch_bounds__(256) scatter_k(const int* __restrict__ ei, int E,
                                                 int nT8, int Etail) {
    int i = blockIdx.x * 256 + threadIdx.x;
    if (i < nT8) {
        const int4* s4 = (const int4*)ei;
        const int4* d4 = (const int4*)(ei + E);
        int4 s0 = __ldcs(&s4[2 * i]);
        int4 s1 = __ldcs(&s4[2 * i + 1]);
        int4 t0 = __ldcs(&d4[2 * i]);
        int4 t1 = __ldcs(&d4[2 * i + 1]);
        float q0 = __ldg(&d_q[s0.x]);
        float q1 = __ldg(&d_q[s0.y]);
        float q2 = __ldg(&d_q[s0.z]);
        float q3 = __ldg(&d_q[s0.w]);
        float q4 = __ldg(&d_q[s1.x]);
        float q5 = __ldg(&d_q[s1.y]);
        float q6 = __ldg(&d_q[s1.z]);
        float q7 = __ldg(&d_q[s1.w]);
        atomicAdd(&d_sacc[t0.x], q0);
        atomicAdd(&d_sacc[t0.y], q1);
        atomicAdd(&d_sacc[t0.z], q2);
        atomicAdd(&d_sacc[t0.w], q3);
        atomicAdd(&d_sacc[t1.x], q4);
        atomicAdd(&d_sacc[t1.y], q5);
        atomicAdd(&d_sacc[t1.z], q6);
        atomicAdd(&d_sacc[t1.w], q7);
    }
    if (i == 0)
        for (int k = 0; k < Etail; k++) {
            int e = nT8 * 8 + k;
            atomicAdd(&d_sacc[ei[E + e]], __ldg(&d_q[ei[e]]));
        }
}

// score_k: out[n] = C + dinv[n] * sacc[n], float4-vectorized
__global__ void __launch_bounds__(256) score_k(float* __restrict__ out, int n4, int n) {
    int i = blockIdx.x * 256 + threadIdx.x;
    if (i < n4) {
        float4 dv = ((const float4*)d_dinv)[i];
        float4 sa = ((const float4*)d_sacc)[i];
        float C = d_C;
        float4 o;
        o.x = fmaf(dv.x, sa.x, C);
        o.y = fmaf(dv.y, sa.y, C);
        o.z = fmaf(dv.z, sa.z, C);
        o.w = fmaf(dv.w, sa.w, C);
        ((float4*)out)[i] = o;
    }
    if (i == 0)
        for (int k = n4 * 4; k < n; k++) out[k] = fmaf(d_dinv[k], d_sacc[k], d_C);
}

// ---------------------------------------------------------------------------
extern "C" void kernel_launch(void* const* d_in, const int* in_sizes, int n_in,
                              void* d_out, int out_size) {
    const float* x   = (const float*)d_in[0];
    const int*   ei  = (const int*)d_in[1];      // int32 (JAX x64 disabled)
    const float* w1  = (const float*)d_in[2];
    const float* b1  = (const float*)d_in[3];
    const float* gam = (const float*)d_in[4];
    const float* bet = (const float*)d_in[5];
    const float* pa  = (const float*)d_in[6];
    const float* w2  = (const float*)d_in[7];
    const float* b2  = (const float*)d_in[8];
    const float* gw  = (const float*)d_in[9];
    const float* gb  = (const float*)d_in[10];
    const float* wb  = (const float*)d_in[11];
    const float* bb  = (const float*)d_in[12];
    int n = in_sizes[0] / 2;
    int E = in_sizes[1] / 2;
    int nT8 = E >> 3;                 // 8 edges per thread
    int Etail = E & 7;
    int nbn = (n + 255) / 256;
    int ebn = (nT8 + 255) / 256;
    if (ebn < nbn) ebn = nbn;         // edge grid must cover the stats blocks
    int n4 = n >> 2;

    degstats_k<<<ebn, 256>>>(ei + E, nT8, Etail, E, x, n, nbn);
    encode_k<<<nbn, 256>>>(x, w1, b1, gam, bet, pa, w2, b2, gw, gb, wb, bb, n, nbn);
    scatter_k<<<(nT8 + 255) / 256, 256>>>(ei, E, nT8, Etail);
    score_k<<<(n4 + 255) / 256, 256>>>((float*)d_out, n4, n);
}